// round 6
// baseline (speedup 1.0000x reference)
#include <cuda_runtime.h>
#include <cstdint>

#define B_  4
#define C_  64
#define H_  96
#define W_  96
#define O_  128
#define HW_ (H_*W_)
#define K2_ 9
#define NJ_ 27
#define CK_ (C_*K2_)   // 576
#define CG_ 4
#define CPG (C_/CG_)   // 16

// scratch
__device__ float g_part[(size_t)CG_*B_*NJ_*HW_];
__device__ float g_V[(size_t)B_*CK_*HW_];
__device__ float g_Wt[(size_t)CK_*O_];   // transposed deform weights [k][o]

// ---------------------------------------------------------------------------
// Kernel A: offset+modulator 3x3 conv, partial over 16-channel groups,
// split into two j-halves, 4 pixels per thread.
// ---------------------------------------------------------------------------
template<int JBASE, int JN>
__global__ void __launch_bounds__(256) conv_offmod_partial(
    const float* __restrict__ x, const float* __restrict__ ow,
    const float* __restrict__ mw)
{
    __shared__ float ws[CPG*JN*9];
    __shared__ float xs[34*36];

    const int tx = threadIdx.x;          // 0..7
    const int ty = threadIdx.y;          // 0..31
    const int tid = ty*8 + tx;
    const int b = blockIdx.z / CG_;
    const int g = blockIdx.z % CG_;
    const int c0 = g * CPG;
    const int x0t = blockIdx.x*32 - 1;
    const int y0t = blockIdx.y*32 - 1;

    for (int idx = tid; idx < CPG*JN*9; idx += 256) {
        int c = idx / (JN*9), r = idx % (JN*9);
        int j = r / 9 + JBASE, t = r % 9;
        float v = (j < 18) ? ow[(j*64 + c0 + c)*9 + t]
                           : mw[((j-18)*64 + c0 + c)*9 + t];
        ws[idx] = v;
    }

    float acc[JN][4];
#pragma unroll
    for (int j = 0; j < JN; j++)
#pragma unroll
        for (int i = 0; i < 4; i++) acc[j][i] = 0.f;

    const float* xb = x + (b*C_ + c0)*HW_;

    for (int c = 0; c < CPG; c++) {
        __syncthreads();
        for (int idx = tid; idx < 34*34; idx += 256) {
            int r = idx / 34, cc = idx % 34;
            int gy = y0t + r, gx = x0t + cc;
            float v = 0.f;
            if (gy >= 0 && gy < H_ && gx >= 0 && gx < W_)
                v = xb[c*HW_ + gy*W_ + gx];
            xs[r*36 + cc] = v;
        }
        __syncthreads();

        float xv[3][6];
#pragma unroll
        for (int dy = 0; dy < 3; dy++)
#pragma unroll
            for (int dx = 0; dx < 6; dx++)
                xv[dy][dx] = xs[(ty + dy)*36 + tx*4 + dx];

        const float* wc = ws + c*JN*9;
#pragma unroll
        for (int j = 0; j < JN; j++) {
#pragma unroll
            for (int t = 0; t < 9; t++) {
                float wv = wc[j*9 + t];
#pragma unroll
                for (int i = 0; i < 4; i++)
                    acc[j][i] = fmaf(wv, xv[t/3][t%3 + i], acc[j][i]);
            }
        }
    }

    const int h  = y0t + 1 + ty;
    const int w0 = x0t + 1 + tx*4;
    float* outb = g_part + ((size_t)(g*B_ + b)*NJ_ + JBASE)*HW_ + h*W_ + w0;
#pragma unroll
    for (int j = 0; j < JN; j++) {
        float4 v = make_float4(acc[j][0], acc[j][1], acc[j][2], acc[j][3]);
        *(float4*)(outb + (size_t)j*HW_) = v;
    }
}

// ---------------------------------------------------------------------------
// Kernel T: transpose deform weights [O][CK] -> [CK][O]
// ---------------------------------------------------------------------------
__global__ void transpose_w(const float* __restrict__ dw)
{
    int i = blockIdx.x*256 + threadIdx.x;
    if (i < O_*CK_) {
        int o = i / CK_, k = i % CK_;
        g_Wt[(size_t)k*O_ + o] = dw[i];
    }
}

// ---------------------------------------------------------------------------
// Kernel G: combine partials (+bias/sigmoid), bilinear gather -> g_V
// ---------------------------------------------------------------------------
#define PT 64

__global__ void gather_kernel(
    const float* __restrict__ x, const float* __restrict__ ob,
    const float* __restrict__ mb)
{
    __shared__ float wgt[4*K2_*PT];
    __shared__ int   gof[4*K2_*PT];

    const int tid = threadIdx.x;
    const int b   = blockIdx.y;
    const int pg0 = blockIdx.x * PT;

    const float* xb = x + b*C_*HW_;

    for (int t = tid; t < K2_*PT; t += 256) {
        int k2 = t / PT, p = t % PT;
        int pg = pg0 + p;
        int h  = pg / W_, w = pg % W_;

        float dy = ob[2*k2], dx = ob[2*k2+1], mv = mb[k2];
#pragma unroll
        for (int g = 0; g < CG_; g++) {
            const float* pb = g_part + (((size_t)g*B_ + b)*NJ_)*HW_ + pg;
            dy += pb[(size_t)(2*k2)*HW_];
            dx += pb[(size_t)(2*k2+1)*HW_];
            mv += pb[(size_t)(18+k2)*HW_];
        }
        float m = 2.f / (1.f + __expf(-mv));

        float py = (float)(h - 1 + k2/3) + dy;
        float px = (float)(w - 1 + k2%3) + dx;
        float fy = floorf(py), fx = floorf(px);
        float ly = py - fy,    lx = px - fx;
        int y0 = (int)fy, x0i = (int)fx;
        float vy0 = (y0   >= 0 && y0   < H_) ? 1.f : 0.f;
        float vy1 = (y0+1 >= 0 && y0+1 < H_) ? 1.f : 0.f;
        float vx0 = (x0i   >= 0 && x0i   < W_) ? 1.f : 0.f;
        float vx1 = (x0i+1 >= 0 && x0i+1 < W_) ? 1.f : 0.f;
        int cy0 = min(max(y0, 0), H_-1),   cy1 = min(max(y0+1, 0), H_-1);
        int cx0 = min(max(x0i, 0), W_-1),  cx1 = min(max(x0i+1, 0), W_-1);
        int base = k2*PT + p;
        wgt[0*(K2_*PT) + base] = (1.f-ly)*(1.f-lx)*vy0*vx0*m;
        wgt[1*(K2_*PT) + base] = (1.f-ly)*lx      *vy0*vx1*m;
        wgt[2*(K2_*PT) + base] = ly*(1.f-lx)      *vy1*vx0*m;
        wgt[3*(K2_*PT) + base] = ly*lx            *vy1*vx1*m;
        gof[0*(K2_*PT) + base] = cy0*W_ + cx0;
        gof[1*(K2_*PT) + base] = cy0*W_ + cx1;
        gof[2*(K2_*PT) + base] = cy1*W_ + cx0;
        gof[3*(K2_*PT) + base] = cy1*W_ + cx1;
    }
    __syncthreads();

    const int p  = tid % PT;
    const int kr = tid / PT;   // 0..3
    float* Vb = g_V + (size_t)b*CK_*HW_ + pg0 + p;

#pragma unroll 4
    for (int k = kr; k < CK_; k += 4) {
        int c = k / K2_, k2 = k % K2_;
        const float* xc = xb + c*HW_;
        int base = k2*PT + p;
        float v = wgt[0*(K2_*PT) + base] * __ldg(xc + gof[0*(K2_*PT) + base])
                + wgt[1*(K2_*PT) + base] * __ldg(xc + gof[1*(K2_*PT) + base])
                + wgt[2*(K2_*PT) + base] * __ldg(xc + gof[2*(K2_*PT) + base])
                + wgt[3*(K2_*PT) + base] * __ldg(xc + gof[3*(K2_*PT) + base]);
        Vb[(size_t)k*HW_] = v;
    }
}

// ---------------------------------------------------------------------------
// Kernel M: GEMM out[b][o][p] = sum_k Wt[k][o] * V[b][k][p]
// 128o x 64p tile, 256 threads, thread tile 4p x 8o, FFMA2.
// cp.async double-buffered K-chunks (KCM=64).
// ---------------------------------------------------------------------------
#define KCM 64
#define PTM 64
#define WS_FLOATS (KCM*O_)       // 8192 per buffer
#define VS_FLOATS (KCM*PTM)      // 4096 per buffer
#define VOFF (2*WS_FLOATS)       // Vs base offset in smem floats

__device__ __forceinline__ void cp16(float* s, const float* g) {
    unsigned sa = (unsigned)__cvta_generic_to_shared(s);
    asm volatile("cp.async.cg.shared.global [%0], [%1], 16;"
                 :: "r"(sa), "l"(g));
}
__device__ __forceinline__ unsigned long long pack2(float v) {
    unsigned long long r;
    unsigned int u = __float_as_uint(v);
    asm("mov.b64 %0, {%1, %1};" : "=l"(r) : "r"(u));
    return r;
}
__device__ __forceinline__ unsigned long long pair2(float a, float b) {
    unsigned long long r;
    asm("mov.b64 %0, {%1, %2};" : "=l"(r) : "f"(a), "f"(b));
    return r;
}

__global__ void __launch_bounds__(256) gemm_kernel(float* __restrict__ out)
{
    extern __shared__ float sm[];   // Ws[2][64][128] | Vs[2][64][64]

    const int tid = threadIdx.x;
    const int b   = blockIdx.y;
    const int px0 = blockIdx.x * PTM;

    const int to = tid & 15;
    const int tp = tid >> 4;
    const int o0 = to * 8;
    const int p0 = tp * 4;

    const float* Vb = g_V + (size_t)b*CK_*HW_ + px0;

    unsigned long long acc2[4][4];   // [p][o-pair]
#pragma unroll
    for (int i = 0; i < 4; i++)
#pragma unroll
        for (int j = 0; j < 4; j++) acc2[i][j] = 0ull;

    // per-thread copy descriptors
    // Ws: 2048 float4 -> 8 per thread ; Vs: 1024 float4 -> 4 per thread
    auto issue = [&](int buf, int kc) {
        float* wbuf = sm + buf*WS_FLOATS;
        float* vbuf = sm + VOFF + buf*VS_FLOATS;
        const float* wg = g_Wt + (size_t)kc*O_;
#pragma unroll
        for (int i = 0; i < 8; i++) {
            int idx = tid + i*256;           // 0..2047
            int r = idx >> 5, q = idx & 31;
            cp16(wbuf + r*O_ + q*4, wg + r*O_ + q*4);
        }
#pragma unroll
        for (int i = 0; i < 4; i++) {
            int idx = tid + i*256;           // 0..1023
            int r = idx >> 4, q = idx & 15;
            cp16(vbuf + r*PTM + q*4, Vb + (size_t)(kc + r)*HW_ + q*4);
        }
        asm volatile("cp.async.commit_group;");
    };

    issue(0, 0);
    int buf = 0;

    const int NCH = CK_/KCM;   // 9
    for (int c = 0; c < NCH; c++) {
        if (c + 1 < NCH) {
            issue(buf ^ 1, (c+1)*KCM);
            asm volatile("cp.async.wait_group 1;");
        } else {
            asm volatile("cp.async.wait_group 0;");
        }
        __syncthreads();

        const float* wbuf = sm + buf*WS_FLOATS;
        const float* vbuf = sm + VOFF + buf*VS_FLOATS;

#pragma unroll 4
        for (int kk = 0; kk < KCM; kk++) {
            const float* wr = wbuf + kk*O_ + o0;
            float4 w0 = *(const float4*)(wr);
            float4 w1 = *(const float4*)(wr + 4);
            float4 vv = *(const float4*)(vbuf + kk*PTM + p0);
            unsigned long long wp0 = pair2(w0.x, w0.y);
            unsigned long long wp1 = pair2(w0.z, w0.w);
            unsigned long long wp2 = pair2(w1.x, w1.y);
            unsigned long long wp3 = pair2(w1.z, w1.w);
            unsigned long long vp[4] = {pack2(vv.x), pack2(vv.y),
                                        pack2(vv.z), pack2(vv.w)};
#pragma unroll
            for (int i = 0; i < 4; i++) {
                asm("fma.rn.f32x2 %0, %1, %2, %0;" : "+l"(acc2[i][0]) : "l"(vp[i]), "l"(wp0));
                asm("fma.rn.f32x2 %0, %1, %2, %0;" : "+l"(acc2[i][1]) : "l"(vp[i]), "l"(wp1));
                asm("fma.rn.f32x2 %0, %1, %2, %0;" : "+l"(acc2[i][2]) : "l"(vp[i]), "l"(wp2));
                asm("fma.rn.f32x2 %0, %1, %2, %0;" : "+l"(acc2[i][3]) : "l"(vp[i]), "l"(wp3));
            }
        }
        __syncthreads();
        buf ^= 1;
    }

    // epilogue: acc2[p][j] holds (o0+2j, o0+2j+1) for pixel p0+p
#pragma unroll
    for (int j = 0; j < 4; j++) {
        float lo[4], hi[4];
#pragma unroll
        for (int i = 0; i < 4; i++) {
            float2 f2 = *(float2*)(&acc2[i][j]);
            lo[i] = f2.x; hi[i] = f2.y;
        }
        float* d0 = out + (size_t)(b*O_ + o0 + 2*j)*HW_ + px0 + p0;
        float* d1 = d0 + HW_;
        *(float4*)d0 = make_float4(lo[0], lo[1], lo[2], lo[3]);
        *(float4*)d1 = make_float4(hi[0], hi[1], hi[2], hi[3]);
    }
}

// ---------------------------------------------------------------------------
extern "C" void kernel_launch(void* const* d_in, const int* in_sizes, int n_in,
                              void* d_out, int out_size)
{
    const float* x  = (const float*)d_in[0];
    const float* ow = (const float*)d_in[1];
    const float* ob = (const float*)d_in[2];
    const float* mw = (const float*)d_in[3];
    const float* mb = (const float*)d_in[4];
    const float* dw = (const float*)d_in[5];
    float* out = (float*)d_out;

    const int smemM = (2*WS_FLOATS + 2*VS_FLOATS) * 4;   // 96KB
    cudaFuncSetAttribute(gemm_kernel,
                         cudaFuncAttributeMaxDynamicSharedMemorySize, smemM);

    dim3 gA(3, 3, B_*CG_), bA(8, 32);
    conv_offmod_partial<0,14><<<gA, bA>>>(x, ow, mw);
    conv_offmod_partial<14,13><<<gA, bA>>>(x, ow, mw);

    transpose_w<<<(O_*CK_ + 255)/256, 256>>>(dw);

    dim3 gG(HW_/PT, B_);
    gather_kernel<<<gG, 256>>>(x, ob, mb);

    dim3 gM(HW_/PTM, B_);   // 144 x 4 = 576 blocks
    gemm_kernel<<<gM, 256, smemM>>>(out);
}

// round 7
// speedup vs baseline: 1.2372x; 1.2372x over previous
#include <cuda_runtime.h>
#include <cstdint>

#define B_  4
#define C_  64
#define H_  96
#define W_  96
#define O_  128
#define HW_ (H_*W_)
#define K2_ 9
#define NJ_ 27
#define CK_ (C_*K2_)   // 576
#define CG_ 4
#define CPG (C_/CG_)   // 16

// scratch
__device__ float g_part[(size_t)CG_*B_*NJ_*HW_];
__device__ float g_V[(size_t)B_*CK_*HW_];
__device__ float g_Wt[(size_t)CK_*O_];   // transposed deform weights [k][o]

// ---------------------------------------------------------------------------
// Kernel A: offset+modulator 3x3 conv, partial over 16-channel groups,
// split into two j-halves, 4 pixels per thread.
// ---------------------------------------------------------------------------
template<int JBASE, int JN>
__global__ void __launch_bounds__(256) conv_offmod_partial(
    const float* __restrict__ x, const float* __restrict__ ow,
    const float* __restrict__ mw)
{
    __shared__ float ws[CPG*JN*9];
    __shared__ float xs[34*36];

    const int tx = threadIdx.x;          // 0..7
    const int ty = threadIdx.y;          // 0..31
    const int tid = ty*8 + tx;
    const int b = blockIdx.z / CG_;
    const int g = blockIdx.z % CG_;
    const int c0 = g * CPG;
    const int x0t = blockIdx.x*32 - 1;
    const int y0t = blockIdx.y*32 - 1;

    for (int idx = tid; idx < CPG*JN*9; idx += 256) {
        int c = idx / (JN*9), r = idx % (JN*9);
        int j = r / 9 + JBASE, t = r % 9;
        float v = (j < 18) ? ow[(j*64 + c0 + c)*9 + t]
                           : mw[((j-18)*64 + c0 + c)*9 + t];
        ws[idx] = v;
    }

    float acc[JN][4];
#pragma unroll
    for (int j = 0; j < JN; j++)
#pragma unroll
        for (int i = 0; i < 4; i++) acc[j][i] = 0.f;

    const float* xb = x + (b*C_ + c0)*HW_;

    for (int c = 0; c < CPG; c++) {
        __syncthreads();
        for (int idx = tid; idx < 34*34; idx += 256) {
            int r = idx / 34, cc = idx % 34;
            int gy = y0t + r, gx = x0t + cc;
            float v = 0.f;
            if (gy >= 0 && gy < H_ && gx >= 0 && gx < W_)
                v = xb[c*HW_ + gy*W_ + gx];
            xs[r*36 + cc] = v;
        }
        __syncthreads();

        float xv[3][6];
#pragma unroll
        for (int dy = 0; dy < 3; dy++)
#pragma unroll
            for (int dx = 0; dx < 6; dx++)
                xv[dy][dx] = xs[(ty + dy)*36 + tx*4 + dx];

        const float* wc = ws + c*JN*9;
#pragma unroll
        for (int j = 0; j < JN; j++) {
#pragma unroll
            for (int t = 0; t < 9; t++) {
                float wv = wc[j*9 + t];
#pragma unroll
                for (int i = 0; i < 4; i++)
                    acc[j][i] = fmaf(wv, xv[t/3][t%3 + i], acc[j][i]);
            }
        }
    }

    const int h  = y0t + 1 + ty;
    const int w0 = x0t + 1 + tx*4;
    float* outb = g_part + ((size_t)(g*B_ + b)*NJ_ + JBASE)*HW_ + h*W_ + w0;
#pragma unroll
    for (int j = 0; j < JN; j++) {
        float4 v = make_float4(acc[j][0], acc[j][1], acc[j][2], acc[j][3]);
        *(float4*)(outb + (size_t)j*HW_) = v;
    }
}

// ---------------------------------------------------------------------------
// Kernel T: transpose deform weights [O][CK] -> [CK][O]
// ---------------------------------------------------------------------------
__global__ void transpose_w(const float* __restrict__ dw)
{
    int i = blockIdx.x*256 + threadIdx.x;
    if (i < O_*CK_) {
        int o = i / CK_, k = i % CK_;
        g_Wt[(size_t)k*O_ + o] = dw[i];
    }
}

// ---------------------------------------------------------------------------
// Kernel G: combine partials (+bias/sigmoid), bilinear gather -> g_V
// ---------------------------------------------------------------------------
#define PT 64

__global__ void gather_kernel(
    const float* __restrict__ x, const float* __restrict__ ob,
    const float* __restrict__ mb)
{
    __shared__ float wgt[4*K2_*PT];
    __shared__ int   gof[4*K2_*PT];

    const int tid = threadIdx.x;
    const int b   = blockIdx.y;
    const int pg0 = blockIdx.x * PT;

    const float* xb = x + b*C_*HW_;

    for (int t = tid; t < K2_*PT; t += 256) {
        int k2 = t / PT, p = t % PT;
        int pg = pg0 + p;
        int h  = pg / W_, w = pg % W_;

        float dy = ob[2*k2], dx = ob[2*k2+1], mv = mb[k2];
#pragma unroll
        for (int g = 0; g < CG_; g++) {
            const float* pb = g_part + (((size_t)g*B_ + b)*NJ_)*HW_ + pg;
            dy += pb[(size_t)(2*k2)*HW_];
            dx += pb[(size_t)(2*k2+1)*HW_];
            mv += pb[(size_t)(18+k2)*HW_];
        }
        float m = 2.f / (1.f + __expf(-mv));

        float py = (float)(h - 1 + k2/3) + dy;
        float px = (float)(w - 1 + k2%3) + dx;
        float fy = floorf(py), fx = floorf(px);
        float ly = py - fy,    lx = px - fx;
        int y0 = (int)fy, x0i = (int)fx;
        float vy0 = (y0   >= 0 && y0   < H_) ? 1.f : 0.f;
        float vy1 = (y0+1 >= 0 && y0+1 < H_) ? 1.f : 0.f;
        float vx0 = (x0i   >= 0 && x0i   < W_) ? 1.f : 0.f;
        float vx1 = (x0i+1 >= 0 && x0i+1 < W_) ? 1.f : 0.f;
        int cy0 = min(max(y0, 0), H_-1),   cy1 = min(max(y0+1, 0), H_-1);
        int cx0 = min(max(x0i, 0), W_-1),  cx1 = min(max(x0i+1, 0), W_-1);
        int base = k2*PT + p;
        wgt[0*(K2_*PT) + base] = (1.f-ly)*(1.f-lx)*vy0*vx0*m;
        wgt[1*(K2_*PT) + base] = (1.f-ly)*lx      *vy0*vx1*m;
        wgt[2*(K2_*PT) + base] = ly*(1.f-lx)      *vy1*vx0*m;
        wgt[3*(K2_*PT) + base] = ly*lx            *vy1*vx1*m;
        gof[0*(K2_*PT) + base] = cy0*W_ + cx0;
        gof[1*(K2_*PT) + base] = cy0*W_ + cx1;
        gof[2*(K2_*PT) + base] = cy1*W_ + cx0;
        gof[3*(K2_*PT) + base] = cy1*W_ + cx1;
    }
    __syncthreads();

    const int p  = tid % PT;
    const int kr = tid / PT;   // 0..3
    float* Vb = g_V + (size_t)b*CK_*HW_ + pg0 + p;

#pragma unroll 4
    for (int k = kr; k < CK_; k += 4) {
        int c = k / K2_, k2 = k % K2_;
        const float* xc = xb + c*HW_;
        int base = k2*PT + p;
        float v = wgt[0*(K2_*PT) + base] * __ldg(xc + gof[0*(K2_*PT) + base])
                + wgt[1*(K2_*PT) + base] * __ldg(xc + gof[1*(K2_*PT) + base])
                + wgt[2*(K2_*PT) + base] * __ldg(xc + gof[2*(K2_*PT) + base])
                + wgt[3*(K2_*PT) + base] * __ldg(xc + gof[3*(K2_*PT) + base]);
        Vb[(size_t)k*HW_] = v;
    }
}

// ---------------------------------------------------------------------------
// Kernel M: GEMM out[b][o][p] = sum_k Wt[k][o] * V[b][k][p]
// 128o x 128p tile, 256 threads, 8o x 8p thread tile, FFMA2.
// cp.async double-buffered K-chunks (KCM=32), both tiles row copies.
// ---------------------------------------------------------------------------
#define KCM 32
#define WS_FLOATS (KCM*O_)      // 4096 per buffer
#define VS_FLOATS (KCM*128)     // 4096 per buffer
#define VOFF (2*WS_FLOATS)

__device__ __forceinline__ void cp16(float* s, const float* g) {
    unsigned sa = (unsigned)__cvta_generic_to_shared(s);
    asm volatile("cp.async.cg.shared.global [%0], [%1], 16;"
                 :: "r"(sa), "l"(g));
}
__device__ __forceinline__ unsigned long long pack2(float v) {
    unsigned long long r;
    unsigned int u = __float_as_uint(v);
    asm("mov.b64 %0, {%1, %1};" : "=l"(r) : "r"(u));
    return r;
}

__global__ void __launch_bounds__(256) gemm_kernel(float* __restrict__ out)
{
    extern __shared__ float sm[];   // Ws[2][32][128] | Vs[2][32][128]

    const int tid = threadIdx.x;
    const int b   = blockIdx.y;
    const int px0 = blockIdx.x * 128;

    const int to = tid & 15;
    const int tp = tid >> 4;
    const int o0 = to * 8;
    const int p0 = tp * 8;

    const float* Vb = g_V + (size_t)b*CK_*HW_ + px0;

    unsigned long long acc2[8][4];   // [o][p-pair]
#pragma unroll
    for (int i = 0; i < 8; i++)
#pragma unroll
        for (int j = 0; j < 4; j++) acc2[i][j] = 0ull;

    // per chunk: Ws 1024 float4 (4/thread), Vs 1024 float4 (4/thread)
    auto issue = [&](int buf, int kc) {
        float* wbuf = sm + buf*WS_FLOATS;
        float* vbuf = sm + VOFF + buf*VS_FLOATS;
        const float* wg = g_Wt + (size_t)kc*O_;
#pragma unroll
        for (int i = 0; i < 4; i++) {
            int idx = tid + i*256;          // 0..1023
            int r = idx >> 5, q = idx & 31;
            cp16(wbuf + r*O_ + q*4, wg + r*O_ + q*4);
        }
#pragma unroll
        for (int i = 0; i < 4; i++) {
            int idx = tid + i*256;          // 0..1023
            int r = idx >> 5, q = idx & 31;
            cp16(vbuf + r*128 + q*4, Vb + (size_t)(kc + r)*HW_ + q*4);
        }
        asm volatile("cp.async.commit_group;");
    };

    issue(0, 0);
    int buf = 0;

    const int NCH = CK_/KCM;   // 18
    for (int c = 0; c < NCH; c++) {
        if (c + 1 < NCH) {
            issue(buf ^ 1, (c+1)*KCM);
            asm volatile("cp.async.wait_group 1;");
        } else {
            asm volatile("cp.async.wait_group 0;");
        }
        __syncthreads();

        const float* wbuf = sm + buf*WS_FLOATS;
        const float* vbuf = sm + VOFF + buf*VS_FLOATS;

#pragma unroll 4
        for (int kk = 0; kk < KCM; kk++) {
            const float* wr = wbuf + kk*O_ + o0;
            float4 a0 = *(const float4*)(wr);
            float4 a1 = *(const float4*)(wr + 4);
            const unsigned long long* vr =
                (const unsigned long long*)(vbuf + kk*128 + p0);
            unsigned long long bv0 = vr[0], bv1 = vr[1], bv2 = vr[2], bv3 = vr[3];
            float av[8] = {a0.x, a0.y, a0.z, a0.w, a1.x, a1.y, a1.z, a1.w};
#pragma unroll
            for (int i = 0; i < 8; i++) {
                unsigned long long ai = pack2(av[i]);
                asm("fma.rn.f32x2 %0, %1, %2, %0;" : "+l"(acc2[i][0]) : "l"(ai), "l"(bv0));
                asm("fma.rn.f32x2 %0, %1, %2, %0;" : "+l"(acc2[i][1]) : "l"(ai), "l"(bv1));
                asm("fma.rn.f32x2 %0, %1, %2, %0;" : "+l"(acc2[i][2]) : "l"(ai), "l"(bv2));
                asm("fma.rn.f32x2 %0, %1, %2, %0;" : "+l"(acc2[i][3]) : "l"(ai), "l"(bv3));
            }
        }
        __syncthreads();
        buf ^= 1;
    }

    // epilogue: acc2[i][*] = pixels p0..p0+7 for output channel o0+i
#pragma unroll
    for (int i = 0; i < 8; i++) {
        float* dst = out + (size_t)(b*O_ + o0 + i)*HW_ + px0 + p0;
        *(float4*)(dst)     = *(float4*)(&acc2[i][0]);
        *(float4*)(dst + 4) = *(float4*)(&acc2[i][2]);
    }
}

// ---------------------------------------------------------------------------
extern "C" void kernel_launch(void* const* d_in, const int* in_sizes, int n_in,
                              void* d_out, int out_size)
{
    const float* x  = (const float*)d_in[0];
    const float* ow = (const float*)d_in[1];
    const float* ob = (const float*)d_in[2];
    const float* mw = (const float*)d_in[3];
    const float* mb = (const float*)d_in[4];
    const float* dw = (const float*)d_in[5];
    float* out = (float*)d_out;

    const int smemM = (2*WS_FLOATS + 2*VS_FLOATS) * 4;   // 64KB
    cudaFuncSetAttribute(gemm_kernel,
                         cudaFuncAttributeMaxDynamicSharedMemorySize, smemM);

    dim3 gA(3, 3, B_*CG_), bA(8, 32);
    conv_offmod_partial<0,14><<<gA, bA>>>(x, ow, mw);
    conv_offmod_partial<14,13><<<gA, bA>>>(x, ow, mw);

    transpose_w<<<(O_*CK_ + 255)/256, 256>>>(dw);

    dim3 gG(HW_/PT, B_);
    gather_kernel<<<gG, 256>>>(x, ob, mb);

    dim3 gM(HW_/128, B_);   // 72 x 4 = 288 blocks
    gemm_kernel<<<gM, 256, smemM>>>(out);
}

// round 8
// speedup vs baseline: 1.5180x; 1.2270x over previous
#include <cuda_runtime.h>
#include <cstdint>

#define B_  4
#define C_  64
#define H_  96
#define W_  96
#define O_  128
#define HW_ (H_*W_)
#define K2_ 9
#define NJ_ 27
#define CK_ (C_*K2_)   // 576
#define CG_ 4
#define CPG (C_/CG_)   // 16

// scratch
__device__ float g_part[(size_t)CG_*B_*NJ_*HW_];
__device__ float g_V[(size_t)B_*CK_*HW_];
__device__ float g_Wt[(size_t)CK_*O_];   // transposed deform weights [k][o]

// ---------------------------------------------------------------------------
// Kernel A: offset+modulator 3x3 conv, partial over 16-channel groups,
// BOTH j-halves in one launch (half from blockIdx.z). 4 pixels/thread.
// grid (3,3,B*CG*2) = 288 blocks -> one full wave at 2 blocks/SM.
// ---------------------------------------------------------------------------
__global__ void __launch_bounds__(256) conv_offmod_partial(
    const float* __restrict__ x, const float* __restrict__ ow,
    const float* __restrict__ mw)
{
    __shared__ float ws[CPG*14*9];
    __shared__ float xs[34*36];

    const int tx = threadIdx.x;          // 0..7
    const int ty = threadIdx.y;          // 0..31
    const int tid = ty*8 + tx;
    const int zz = blockIdx.z;           // 0..31
    const int half = zz & 1;
    const int g = (zz >> 1) & 3;
    const int b = zz >> 3;
    const int JB = half * 14;
    const int jn = half ? 13 : 14;
    const int c0 = g * CPG;
    const int x0t = blockIdx.x*32 - 1;
    const int y0t = blockIdx.y*32 - 1;

    const int jn9 = jn * 9;
    for (int idx = tid; idx < CPG*jn9; idx += 256) {
        int c = idx / jn9, r = idx % jn9;
        int j = r / 9 + JB, t = r % 9;
        float v = (j < 18) ? ow[(j*64 + c0 + c)*9 + t]
                           : mw[((j-18)*64 + c0 + c)*9 + t];
        ws[idx] = v;
    }

    float acc[14][4];
#pragma unroll
    for (int j = 0; j < 14; j++)
#pragma unroll
        for (int i = 0; i < 4; i++) acc[j][i] = 0.f;

    const float* xb = x + (b*C_ + c0)*HW_;

    for (int c = 0; c < CPG; c++) {
        __syncthreads();
        for (int idx = tid; idx < 34*34; idx += 256) {
            int r = idx / 34, cc = idx % 34;
            int gy = y0t + r, gx = x0t + cc;
            float v = 0.f;
            if (gy >= 0 && gy < H_ && gx >= 0 && gx < W_)
                v = xb[c*HW_ + gy*W_ + gx];
            xs[r*36 + cc] = v;
        }
        __syncthreads();

        float xv[3][6];
#pragma unroll
        for (int dy = 0; dy < 3; dy++)
#pragma unroll
            for (int dx = 0; dx < 6; dx++)
                xv[dy][dx] = xs[(ty + dy)*36 + tx*4 + dx];

        const float* wc = ws + c*jn9;
#pragma unroll
        for (int j = 0; j < 14; j++) {
            if (j < jn) {
#pragma unroll
                for (int t = 0; t < 9; t++) {
                    float wv = wc[j*9 + t];
#pragma unroll
                    for (int i = 0; i < 4; i++)
                        acc[j][i] = fmaf(wv, xv[t/3][t%3 + i], acc[j][i]);
                }
            }
        }
    }

    const int h  = y0t + 1 + ty;
    const int w0 = x0t + 1 + tx*4;
    float* outb = g_part + ((size_t)(g*B_ + b)*NJ_ + JB)*HW_ + h*W_ + w0;
#pragma unroll
    for (int j = 0; j < 14; j++) {
        if (j < jn) {
            float4 v = make_float4(acc[j][0], acc[j][1], acc[j][2], acc[j][3]);
            *(float4*)(outb + (size_t)j*HW_) = v;
        }
    }
}

// ---------------------------------------------------------------------------
// Kernel T: transpose deform weights [O][CK] -> [CK][O]
// ---------------------------------------------------------------------------
__global__ void transpose_w(const float* __restrict__ dw)
{
    int i = blockIdx.x*256 + threadIdx.x;
    if (i < O_*CK_) {
        int o = i / CK_, k = i % CK_;
        g_Wt[(size_t)k*O_ + o] = dw[i];
    }
}

// ---------------------------------------------------------------------------
// Kernel G: combine partials (+bias/sigmoid), bilinear gather -> g_V
// Stage 1 reordered: k2 outer (params in registers), c inner (pointer adds).
// ---------------------------------------------------------------------------
#define PT 64

__global__ void gather_kernel(
    const float* __restrict__ x, const float* __restrict__ ob,
    const float* __restrict__ mb)
{
    __shared__ float wgt[4*K2_*PT];
    __shared__ int   gof[4*K2_*PT];

    const int tid = threadIdx.x;
    const int b   = blockIdx.y;
    const int pg0 = blockIdx.x * PT;

    const float* xb = x + b*C_*HW_;

    for (int t = tid; t < K2_*PT; t += 256) {
        int k2 = t / PT, p = t % PT;
        int pg = pg0 + p;
        int h  = pg / W_, w = pg % W_;

        float dy = ob[2*k2], dx = ob[2*k2+1], mv = mb[k2];
#pragma unroll
        for (int g = 0; g < CG_; g++) {
            const float* pb = g_part + (((size_t)g*B_ + b)*NJ_)*HW_ + pg;
            dy += pb[(size_t)(2*k2)*HW_];
            dx += pb[(size_t)(2*k2+1)*HW_];
            mv += pb[(size_t)(18+k2)*HW_];
        }
        float m = 2.f / (1.f + __expf(-mv));

        float py = (float)(h - 1 + k2/3) + dy;
        float px = (float)(w - 1 + k2%3) + dx;
        float fy = floorf(py), fx = floorf(px);
        float ly = py - fy,    lx = px - fx;
        int y0 = (int)fy, x0i = (int)fx;
        float vy0 = (y0   >= 0 && y0   < H_) ? 1.f : 0.f;
        float vy1 = (y0+1 >= 0 && y0+1 < H_) ? 1.f : 0.f;
        float vx0 = (x0i   >= 0 && x0i   < W_) ? 1.f : 0.f;
        float vx1 = (x0i+1 >= 0 && x0i+1 < W_) ? 1.f : 0.f;
        int cy0 = min(max(y0, 0), H_-1),   cy1 = min(max(y0+1, 0), H_-1);
        int cx0 = min(max(x0i, 0), W_-1),  cx1 = min(max(x0i+1, 0), W_-1);
        int base = k2*PT + p;
        wgt[0*(K2_*PT) + base] = (1.f-ly)*(1.f-lx)*vy0*vx0*m;
        wgt[1*(K2_*PT) + base] = (1.f-ly)*lx      *vy0*vx1*m;
        wgt[2*(K2_*PT) + base] = ly*(1.f-lx)      *vy1*vx0*m;
        wgt[3*(K2_*PT) + base] = ly*lx            *vy1*vx1*m;
        gof[0*(K2_*PT) + base] = cy0*W_ + cx0;
        gof[1*(K2_*PT) + base] = cy0*W_ + cx1;
        gof[2*(K2_*PT) + base] = cy1*W_ + cx0;
        gof[3*(K2_*PT) + base] = cy1*W_ + cx1;
    }
    __syncthreads();

    const int p  = tid & 63;
    const int kr = tid >> 6;   // 0..3
    float* Vb = g_V + (size_t)b*CK_*HW_ + pg0 + p;

#pragma unroll
    for (int k2 = 0; k2 < K2_; k2++) {
        int base = k2*PT + p;
        float w0 = wgt[0*(K2_*PT) + base];
        float w1 = wgt[1*(K2_*PT) + base];
        float w2 = wgt[2*(K2_*PT) + base];
        float w3 = wgt[3*(K2_*PT) + base];
        const float* p0 = xb + kr*HW_ + gof[0*(K2_*PT) + base];
        const float* p1 = xb + kr*HW_ + gof[1*(K2_*PT) + base];
        const float* p2 = xb + kr*HW_ + gof[2*(K2_*PT) + base];
        const float* p3 = xb + kr*HW_ + gof[3*(K2_*PT) + base];
        float* op = Vb + (size_t)(kr*K2_ + k2)*HW_;

#pragma unroll 4
        for (int c = kr; c < C_; c += 4) {
            float v = w0*__ldg(p0) + w1*__ldg(p1)
                    + w2*__ldg(p2) + w3*__ldg(p3);
            *op = v;
            p0 += 4*HW_; p1 += 4*HW_; p2 += 4*HW_; p3 += 4*HW_;
            op += (size_t)4*K2_*HW_;
        }
    }
}

// ---------------------------------------------------------------------------
// Kernel M: GEMM out[b][o][p] = sum_k Wt[k][o] * V[b][k][p]
// 128o x 128p tile, 256 threads, 8o x 8p thread tile, FFMA2.
// cp.async double-buffered K-chunks (KCM=32), both tiles row copies.
// ---------------------------------------------------------------------------
#define KCM 32
#define WS_FLOATS (KCM*O_)      // 4096 per buffer
#define VS_FLOATS (KCM*128)     // 4096 per buffer
#define VOFF (2*WS_FLOATS)

__device__ __forceinline__ void cp16(float* s, const float* g) {
    unsigned sa = (unsigned)__cvta_generic_to_shared(s);
    asm volatile("cp.async.cg.shared.global [%0], [%1], 16;"
                 :: "r"(sa), "l"(g));
}
__device__ __forceinline__ unsigned long long pack2(float v) {
    unsigned long long r;
    unsigned int u = __float_as_uint(v);
    asm("mov.b64 %0, {%1, %1};" : "=l"(r) : "r"(u));
    return r;
}

__global__ void __launch_bounds__(256) gemm_kernel(float* __restrict__ out)
{
    extern __shared__ float sm[];   // Ws[2][32][128] | Vs[2][32][128]

    const int tid = threadIdx.x;
    const int b   = blockIdx.y;
    const int px0 = blockIdx.x * 128;

    const int to = tid & 15;
    const int tp = tid >> 4;
    const int o0 = to * 8;
    const int p0 = tp * 8;

    const float* Vb = g_V + (size_t)b*CK_*HW_ + px0;

    unsigned long long acc2[8][4];   // [o][p-pair]
#pragma unroll
    for (int i = 0; i < 8; i++)
#pragma unroll
        for (int j = 0; j < 4; j++) acc2[i][j] = 0ull;

    auto issue = [&](int buf, int kc) {
        float* wbuf = sm + buf*WS_FLOATS;
        float* vbuf = sm + VOFF + buf*VS_FLOATS;
        const float* wg = g_Wt + (size_t)kc*O_;
#pragma unroll
        for (int i = 0; i < 4; i++) {
            int idx = tid + i*256;
            int r = idx >> 5, q = idx & 31;
            cp16(wbuf + r*O_ + q*4, wg + r*O_ + q*4);
        }
#pragma unroll
        for (int i = 0; i < 4; i++) {
            int idx = tid + i*256;
            int r = idx >> 5, q = idx & 31;
            cp16(vbuf + r*128 + q*4, Vb + (size_t)(kc + r)*HW_ + q*4);
        }
        asm volatile("cp.async.commit_group;");
    };

    issue(0, 0);
    int buf = 0;

    const int NCH = CK_/KCM;   // 18
    for (int c = 0; c < NCH; c++) {
        if (c + 1 < NCH) {
            issue(buf ^ 1, (c+1)*KCM);
            asm volatile("cp.async.wait_group 1;");
        } else {
            asm volatile("cp.async.wait_group 0;");
        }
        __syncthreads();

        const float* wbuf = sm + buf*WS_FLOATS;
        const float* vbuf = sm + VOFF + buf*VS_FLOATS;

#pragma unroll 4
        for (int kk = 0; kk < KCM; kk++) {
            const float* wr = wbuf + kk*O_ + o0;
            float4 a0 = *(const float4*)(wr);
            float4 a1 = *(const float4*)(wr + 4);
            const unsigned long long* vr =
                (const unsigned long long*)(vbuf + kk*128 + p0);
            unsigned long long bv0 = vr[0], bv1 = vr[1], bv2 = vr[2], bv3 = vr[3];
            float av[8] = {a0.x, a0.y, a0.z, a0.w, a1.x, a1.y, a1.z, a1.w};
#pragma unroll
            for (int i = 0; i < 8; i++) {
                unsigned long long ai = pack2(av[i]);
                asm("fma.rn.f32x2 %0, %1, %2, %0;" : "+l"(acc2[i][0]) : "l"(ai), "l"(bv0));
                asm("fma.rn.f32x2 %0, %1, %2, %0;" : "+l"(acc2[i][1]) : "l"(ai), "l"(bv1));
                asm("fma.rn.f32x2 %0, %1, %2, %0;" : "+l"(acc2[i][2]) : "l"(ai), "l"(bv2));
                asm("fma.rn.f32x2 %0, %1, %2, %0;" : "+l"(acc2[i][3]) : "l"(ai), "l"(bv3));
            }
        }
        __syncthreads();
        buf ^= 1;
    }

#pragma unroll
    for (int i = 0; i < 8; i++) {
        float* dst = out + (size_t)(b*O_ + o0 + i)*HW_ + px0 + p0;
        *(float4*)(dst)     = *(float4*)(&acc2[i][0]);
        *(float4*)(dst + 4) = *(float4*)(&acc2[i][2]);
    }
}

// ---------------------------------------------------------------------------
extern "C" void kernel_launch(void* const* d_in, const int* in_sizes, int n_in,
                              void* d_out, int out_size)
{
    const float* x  = (const float*)d_in[0];
    const float* ow = (const float*)d_in[1];
    const float* ob = (const float*)d_in[2];
    const float* mw = (const float*)d_in[3];
    const float* mb = (const float*)d_in[4];
    const float* dw = (const float*)d_in[5];
    float* out = (float*)d_out;

    const int smemM = (2*WS_FLOATS + 2*VS_FLOATS) * 4;   // 64KB
    cudaFuncSetAttribute(gemm_kernel,
                         cudaFuncAttributeMaxDynamicSharedMemorySize, smemM);

    dim3 gA(3, 3, B_*CG_*2), bA(8, 32);   // 288 blocks, one launch
    conv_offmod_partial<<<gA, bA>>>(x, ow, mw);

    transpose_w<<<(O_*CK_ + 255)/256, 256>>>(dw);

    dim3 gG(HW_/PT, B_);
    gather_kernel<<<gG, 256>>>(x, ob, mb);

    dim3 gM(HW_/128, B_);   // 72 x 4 = 288 blocks
    gemm_kernel<<<gM, 256, smemM>>>(out);
}

// round 10
// speedup vs baseline: 1.5476x; 1.0195x over previous
#include <cuda_runtime.h>
#include <cstdint>

#define B_  4
#define C_  64
#define H_  96
#define W_  96
#define O_  128
#define HW_ (H_*W_)
#define K2_ 9
#define NJ_ 27
#define CK_ (C_*K2_)   // 576
#define CG_ 4
#define CPG (C_/CG_)   // 16

// scratch
__device__ float g_part[(size_t)CG_*B_*NJ_*HW_];
__device__ float g_V[(size_t)B_*CK_*HW_];
__device__ float g_Wt[(size_t)CK_*O_];   // transposed deform weights [k][o]

// ---------------------------------------------------------------------------
// Kernel A: offset+modulator 3x3 conv, partial over 16-channel groups,
// BOTH j-halves in one launch. 4 pixels/thread. 288 blocks = one full wave.
// ---------------------------------------------------------------------------
__global__ void __launch_bounds__(256) conv_offmod_partial(
    const float* __restrict__ x, const float* __restrict__ ow,
    const float* __restrict__ mw)
{
    __shared__ float ws[CPG*14*9];
    __shared__ float xs[34*36];

    const int tx = threadIdx.x;          // 0..7
    const int ty = threadIdx.y;          // 0..31
    const int tid = ty*8 + tx;
    const int zz = blockIdx.z;           // 0..31
    const int half = zz & 1;
    const int g = (zz >> 1) & 3;
    const int b = zz >> 3;
    const int JB = half * 14;
    const int jn = half ? 13 : 14;
    const int c0 = g * CPG;
    const int x0t = blockIdx.x*32 - 1;
    const int y0t = blockIdx.y*32 - 1;

    const int jn9 = jn * 9;
    for (int idx = tid; idx < CPG*jn9; idx += 256) {
        int c = idx / jn9, r = idx % jn9;
        int j = r / 9 + JB, t = r % 9;
        float v = (j < 18) ? ow[(j*64 + c0 + c)*9 + t]
                           : mw[((j-18)*64 + c0 + c)*9 + t];
        ws[idx] = v;
    }

    float acc[14][4];
#pragma unroll
    for (int j = 0; j < 14; j++)
#pragma unroll
        for (int i = 0; i < 4; i++) acc[j][i] = 0.f;

    const float* xb = x + (b*C_ + c0)*HW_;

    for (int c = 0; c < CPG; c++) {
        __syncthreads();
        for (int idx = tid; idx < 34*34; idx += 256) {
            int r = idx / 34, cc = idx % 34;
            int gy = y0t + r, gx = x0t + cc;
            float v = 0.f;
            if (gy >= 0 && gy < H_ && gx >= 0 && gx < W_)
                v = xb[c*HW_ + gy*W_ + gx];
            xs[r*36 + cc] = v;
        }
        __syncthreads();

        float xv[3][6];
#pragma unroll
        for (int dy = 0; dy < 3; dy++)
#pragma unroll
            for (int dx = 0; dx < 6; dx++)
                xv[dy][dx] = xs[(ty + dy)*36 + tx*4 + dx];

        const float* wc = ws + c*jn9;
#pragma unroll
        for (int j = 0; j < 14; j++) {
            if (j < jn) {
#pragma unroll
                for (int t = 0; t < 9; t++) {
                    float wv = wc[j*9 + t];
#pragma unroll
                    for (int i = 0; i < 4; i++)
                        acc[j][i] = fmaf(wv, xv[t/3][t%3 + i], acc[j][i]);
                }
            }
        }
    }

    const int h  = y0t + 1 + ty;
    const int w0 = x0t + 1 + tx*4;
    float* outb = g_part + ((size_t)(g*B_ + b)*NJ_ + JB)*HW_ + h*W_ + w0;
#pragma unroll
    for (int j = 0; j < 14; j++) {
        if (j < jn) {
            float4 v = make_float4(acc[j][0], acc[j][1], acc[j][2], acc[j][3]);
            *(float4*)(outb + (size_t)j*HW_) = v;
        }
    }
}

// ---------------------------------------------------------------------------
// Kernel T: transpose deform weights [O][CK] -> [CK][O]
// ---------------------------------------------------------------------------
__global__ void transpose_w(const float* __restrict__ dw)
{
    int i = blockIdx.x*256 + threadIdx.x;
    if (i < O_*CK_) {
        int o = i / CK_, k = i % CK_;
        g_Wt[(size_t)k*O_ + o] = dw[i];
    }
}

// ---------------------------------------------------------------------------
// Kernel G: combine partials (+bias/sigmoid), bilinear gather -> g_V
// ---------------------------------------------------------------------------
#define PT 64

__global__ void gather_kernel(
    const float* __restrict__ x, const float* __restrict__ ob,
    const float* __restrict__ mb)
{
    __shared__ float wgt[4*K2_*PT];
    __shared__ int   gof[4*K2_*PT];

    const int tid = threadIdx.x;
    const int b   = blockIdx.y;
    const int pg0 = blockIdx.x * PT;

    const float* xb = x + b*C_*HW_;

    for (int t = tid; t < K2_*PT; t += 256) {
        int k2 = t / PT, p = t % PT;
        int pg = pg0 + p;
        int h  = pg / W_, w = pg % W_;

        float dy = ob[2*k2], dx = ob[2*k2+1], mv = mb[k2];
#pragma unroll
        for (int g = 0; g < CG_; g++) {
            const float* pb = g_part + (((size_t)g*B_ + b)*NJ_)*HW_ + pg;
            dy += pb[(size_t)(2*k2)*HW_];
            dx += pb[(size_t)(2*k2+1)*HW_];
            mv += pb[(size_t)(18+k2)*HW_];
        }
        float m = 2.f / (1.f + __expf(-mv));

        float py = (float)(h - 1 + k2/3) + dy;
        float px = (float)(w - 1 + k2%3) + dx;
        float fy = floorf(py), fx = floorf(px);
        float ly = py - fy,    lx = px - fx;
        int y0 = (int)fy, x0i = (int)fx;
        float vy0 = (y0   >= 0 && y0   < H_) ? 1.f : 0.f;
        float vy1 = (y0+1 >= 0 && y0+1 < H_) ? 1.f : 0.f;
        float vx0 = (x0i   >= 0 && x0i   < W_) ? 1.f : 0.f;
        float vx1 = (x0i+1 >= 0 && x0i+1 < W_) ? 1.f : 0.f;
        int cy0 = min(max(y0, 0), H_-1),   cy1 = min(max(y0+1, 0), H_-1);
        int cx0 = min(max(x0i, 0), W_-1),  cx1 = min(max(x0i+1, 0), W_-1);
        int base = k2*PT + p;
        wgt[0*(K2_*PT) + base] = (1.f-ly)*(1.f-lx)*vy0*vx0*m;
        wgt[1*(K2_*PT) + base] = (1.f-ly)*lx      *vy0*vx1*m;
        wgt[2*(K2_*PT) + base] = ly*(1.f-lx)      *vy1*vx0*m;
        wgt[3*(K2_*PT) + base] = ly*lx            *vy1*vx1*m;
        gof[0*(K2_*PT) + base] = cy0*W_ + cx0;
        gof[1*(K2_*PT) + base] = cy0*W_ + cx1;
        gof[2*(K2_*PT) + base] = cy1*W_ + cx0;
        gof[3*(K2_*PT) + base] = cy1*W_ + cx1;
    }
    __syncthreads();

    const int p  = tid & 63;
    const int kr = tid >> 6;   // 0..3
    float* Vb = g_V + (size_t)b*CK_*HW_ + pg0 + p;

#pragma unroll
    for (int k2 = 0; k2 < K2_; k2++) {
        int base = k2*PT + p;
        float w0 = wgt[0*(K2_*PT) + base];
        float w1 = wgt[1*(K2_*PT) + base];
        float w2 = wgt[2*(K2_*PT) + base];
        float w3 = wgt[3*(K2_*PT) + base];
        const float* p0 = xb + kr*HW_ + gof[0*(K2_*PT) + base];
        const float* p1 = xb + kr*HW_ + gof[1*(K2_*PT) + base];
        const float* p2 = xb + kr*HW_ + gof[2*(K2_*PT) + base];
        const float* p3 = xb + kr*HW_ + gof[3*(K2_*PT) + base];
        float* op = Vb + (size_t)(kr*K2_ + k2)*HW_;

#pragma unroll 4
        for (int c = kr; c < C_; c += 4) {
            float v = w0*__ldg(p0) + w1*__ldg(p1)
                    + w2*__ldg(p2) + w3*__ldg(p3);
            *op = v;
            p0 += 4*HW_; p1 += 4*HW_; p2 += 4*HW_; p3 += 4*HW_;
            op += (size_t)4*K2_*HW_;
        }
    }
}

// ---------------------------------------------------------------------------
// Kernel M: GEMM out[b][o][p] = sum_k Wt[k][o] * V[b][k][p]
// 128o x 128p tile, 256 threads, 8o x 8p thread tile, FFMA2.
// cp.async double-buffered K-chunks (KCM=32).
// NEW: both smem tiles stored with 16B-chunk swizzle sx = cx ^ ((cx>>3)&1)
//      -> W loads drop from 4-way bank conflict to the 2-wavefront floor.
// ---------------------------------------------------------------------------
#define KCM 32
#define WS_FLOATS (KCM*O_)      // 4096 per buffer
#define VS_FLOATS (KCM*128)     // 4096 per buffer
#define VOFF (2*WS_FLOATS)

#define CSWZ(cx) ((cx) ^ (((cx) >> 3) & 1))

__device__ __forceinline__ void cp16(float* s, const float* g) {
    unsigned sa = (unsigned)__cvta_generic_to_shared(s);
    asm volatile("cp.async.cg.shared.global [%0], [%1], 16;"
                 :: "r"(sa), "l"(g));
}
__device__ __forceinline__ unsigned long long pack2(float v) {
    unsigned long long r;
    unsigned int u = __float_as_uint(v);
    asm("mov.b64 %0, {%1, %1};" : "=l"(r) : "r"(u));
    return r;
}

__global__ void __launch_bounds__(256) gemm_kernel(float* __restrict__ out)
{
    extern __shared__ float sm[];   // Ws[2][32][128] | Vs[2][32][128] (chunk-swizzled)

    const int tid = threadIdx.x;
    const int b   = blockIdx.y;
    const int px0 = blockIdx.x * 128;

    const int to = tid & 15;
    const int tp = tid >> 4;
    // swizzled float offsets of this thread's four 16B chunks
    const int wo0 = CSWZ(to*2)     * 4;
    const int wo1 = CSWZ(to*2 + 1) * 4;
    const int vo0 = CSWZ(tp*2)     * 4;
    const int vo1 = CSWZ(tp*2 + 1) * 4;

    const float* Vb = g_V + (size_t)b*CK_*HW_ + px0;

    unsigned long long acc2[8][4];   // [o][p-pair]
#pragma unroll
    for (int i = 0; i < 8; i++)
#pragma unroll
        for (int j = 0; j < 4; j++) acc2[i][j] = 0ull;

    auto issue = [&](int buf, int kc) {
        float* wbuf = sm + buf*WS_FLOATS;
        float* vbuf = sm + VOFF + buf*VS_FLOATS;
        const float* wg = g_Wt + (size_t)kc*O_;
#pragma unroll
        for (int i = 0; i < 4; i++) {
            int idx = tid + i*256;
            int r = idx >> 5, q = idx & 31;
            cp16(wbuf + r*O_ + CSWZ(q)*4, wg + r*O_ + q*4);
        }
#pragma unroll
        for (int i = 0; i < 4; i++) {
            int idx = tid + i*256;
            int r = idx >> 5, q = idx & 31;
            cp16(vbuf + r*128 + CSWZ(q)*4, Vb + (size_t)(kc + r)*HW_ + q*4);
        }
        asm volatile("cp.async.commit_group;");
    };

    issue(0, 0);
    int buf = 0;

    const int NCH = CK_/KCM;   // 18
    for (int c = 0; c < NCH; c++) {
        if (c + 1 < NCH) {
            issue(buf ^ 1, (c+1)*KCM);
            asm volatile("cp.async.wait_group 1;");
        } else {
            asm volatile("cp.async.wait_group 0;");
        }
        __syncthreads();

        const float* wbuf = sm + buf*WS_FLOATS;
        const float* vbuf = sm + VOFF + buf*VS_FLOATS;

#pragma unroll 4
        for (int kk = 0; kk < KCM; kk++) {
            const float* wr = wbuf + kk*O_;
            float4 a0 = *(const float4*)(wr + wo0);
            float4 a1 = *(const float4*)(wr + wo1);
            const float* vr = vbuf + kk*128;
            float4 v0 = *(const float4*)(vr + vo0);
            float4 v1 = *(const float4*)(vr + vo1);
            unsigned long long bv0 = ((const unsigned long long*)&v0)[0];
            unsigned long long bv1 = ((const unsigned long long*)&v0)[1];
            unsigned long long bv2 = ((const unsigned long long*)&v1)[0];
            unsigned long long bv3 = ((const unsigned long long*)&v1)[1];
            float av[8] = {a0.x, a0.y, a0.z, a0.w, a1.x, a1.y, a1.z, a1.w};
#pragma unroll
            for (int i = 0; i < 8; i++) {
                unsigned long long ai = pack2(av[i]);
                asm("fma.rn.f32x2 %0, %1, %2, %0;" : "+l"(acc2[i][0]) : "l"(ai), "l"(bv0));
                asm("fma.rn.f32x2 %0, %1, %2, %0;" : "+l"(acc2[i][1]) : "l"(ai), "l"(bv1));
                asm("fma.rn.f32x2 %0, %1, %2, %0;" : "+l"(acc2[i][2]) : "l"(ai), "l"(bv2));
                asm("fma.rn.f32x2 %0, %1, %2, %0;" : "+l"(acc2[i][3]) : "l"(ai), "l"(bv3));
            }
        }
        __syncthreads();
        buf ^= 1;
    }

    // epilogue: acc2[i][*] = pixels p0..p0+7 for output channel o0+i
    const int o0 = to * 8;
    const int p0 = tp * 8;
#pragma unroll
    for (int i = 0; i < 8; i++) {
        float* dst = out + (size_t)(b*O_ + o0 + i)*HW_ + px0 + p0;
        *(float4*)(dst)     = *(float4*)(&acc2[i][0]);
        *(float4*)(dst + 4) = *(float4*)(&acc2[i][2]);
    }
}

// ---------------------------------------------------------------------------
extern "C" void kernel_launch(void* const* d_in, const int* in_sizes, int n_in,
                              void* d_out, int out_size)
{
    const float* x  = (const float*)d_in[0];
    const float* ow = (const float*)d_in[1];
    const float* ob = (const float*)d_in[2];
    const float* mw = (const float*)d_in[3];
    const float* mb = (const float*)d_in[4];
    const float* dw = (const float*)d_in[5];
    float* out = (float*)d_out;

    const int smemM = (2*WS_FLOATS + 2*VS_FLOATS) * 4;   // 64KB
    cudaFuncSetAttribute(gemm_kernel,
                         cudaFuncAttributeMaxDynamicSharedMemorySize, smemM);

    dim3 gA(3, 3, B_*CG_*2), bA(8, 32);   // 288 blocks, one launch
    conv_offmod_partial<<<gA, bA>>>(x, ow, mw);

    transpose_w<<<(O_*CK_ + 255)/256, 256>>>(dw);

    dim3 gG(HW_/PT, B_);
    gather_kernel<<<gG, 256>>>(x, ob, mb);

    dim3 gM(HW_/128, B_);   // 72 x 4 = 288 blocks
    gemm_kernel<<<gM, 256, smemM>>>(out);
}